// round 1
// baseline (speedup 1.0000x reference)
#include <cuda_runtime.h>
#include <cuda_bf16.h>

#define N_ROWS 8192
#define F_DIM  512
#define K_KEEP 4096

// Scratch (device globals — no allocation allowed)
__device__ __align__(16) float g_y[N_ROWS];     // unnormalized scores X @ kernel
__device__ float g_inv_norm;                    // 1/||kernel||
__device__ __align__(16) int   g_idx[K_KEEP];   // kept indices, ascending

// ---------------------------------------------------------------------------
// Kernel A: y[row] = dot(X[row], kernel)   (one warp per row)
// ---------------------------------------------------------------------------
__global__ __launch_bounds__(256) void compute_y_kernel(
    const float* __restrict__ X, const float* __restrict__ kern)
{
    int warp = threadIdx.x >> 5;
    int lane = threadIdx.x & 31;
    int row  = blockIdx.x * 8 + warp;   // grid = 1024 blocks
    const float4* x4 = (const float4*)(X + (size_t)row * F_DIM);
    const float4* k4 = (const float4*)kern;
    float acc = 0.f;
#pragma unroll
    for (int it = 0; it < 4; it++) {
        int j = lane + 32 * it;         // 128 float4 per row
        float4 x = x4[j];
        float4 k = __ldg(&k4[j]);
        acc = fmaf(x.x, k.x, acc);
        acc = fmaf(x.y, k.y, acc);
        acc = fmaf(x.z, k.z, acc);
        acc = fmaf(x.w, k.w, acc);
    }
#pragma unroll
    for (int o = 16; o > 0; o >>= 1)
        acc += __shfl_xor_sync(0xFFFFFFFFu, acc, o);
    if (lane == 0) g_y[row] = acc;
}

// ---------------------------------------------------------------------------
// Kernel B: single block. Radix-select exact K-th largest key, emit idx[]
// (ascending), compute inv_norm.
// ---------------------------------------------------------------------------
__device__ __forceinline__ int block_exscan(int v, int* s_warp)
{
    __syncthreads();                    // protect s_warp reuse across calls
    int lane = threadIdx.x & 31, warp = threadIdx.x >> 5;
    int incl = v;
#pragma unroll
    for (int o = 1; o < 32; o <<= 1) {
        int t = __shfl_up_sync(0xFFFFFFFFu, incl, o);
        if (lane >= o) incl += t;
    }
    if (lane == 31) s_warp[warp] = incl;
    __syncthreads();
    if (warp == 0) {
        int w  = s_warp[lane];
        int wi = w;
#pragma unroll
        for (int o = 1; o < 32; o <<= 1) {
            int t = __shfl_up_sync(0xFFFFFFFFu, wi, o);
            if (lane >= o) wi += t;
        }
        s_warp[lane] = wi - w;          // exclusive warp offset
    }
    __syncthreads();
    return s_warp[warp] + incl - v;     // exclusive for this thread
}

__global__ __launch_bounds__(1024) void select_kernel(const float* __restrict__ kern)
{
    __shared__ int h0[2048];
    __shared__ int h1[2048];
    __shared__ int s_warp[32];
    __shared__ float s_red[32];
    __shared__ unsigned s_B;
    __shared__ int s_after;

    int tid  = threadIdx.x;
    int lane = tid & 31, warp = tid >> 5;

    // --- load 8 keys per thread (contiguous indices tid*8 .. tid*8+7) ---
    const float4* y4 = (const float4*)g_y;
    float4 a = y4[tid * 2 + 0];
    float4 b = y4[tid * 2 + 1];
    float v[8] = {a.x, a.y, a.z, a.w, b.x, b.y, b.z, b.w};
    unsigned key[8];
#pragma unroll
    for (int j = 0; j < 8; j++) {
        unsigned u = __float_as_uint(v[j]);
        key[j] = (u & 0x80000000u) ? ~u : (u | 0x80000000u); // larger float -> larger key
    }

    // --- inv_norm of kernel vector ---
    float s = 0.f;
    if (tid < F_DIM) { float kv = kern[tid]; s = kv * kv; }
#pragma unroll
    for (int o = 16; o > 0; o >>= 1) s += __shfl_xor_sync(0xFFFFFFFFu, s, o);
    if (lane == 0) s_red[warp] = s;
    __syncthreads();
    if (warp == 0) {
        float t = s_red[lane];
#pragma unroll
        for (int o = 16; o > 0; o >>= 1) t += __shfl_xor_sync(0xFFFFFFFFu, t, o);
        if (lane == 0) s_red[0] = rsqrtf(t);
    }
    __syncthreads();
    float inv_norm = s_red[0];

    // --- 3-pass radix select for exact K-th largest key ---
    const int shifts[3] = {21, 10, 0};
    const int bitsc[3]  = {11, 11, 10};
    unsigned prefix = 0, maskdone = 0;
    int krem = K_KEEP;

#pragma unroll 1
    for (int p = 0; p < 3; p++) {
        int nb = 1 << bitsc[p];
        unsigned bmask = (unsigned)(nb - 1);
        for (int bb = tid; bb < 2048; bb += 1024) h0[bb] = 0;
        __syncthreads();
#pragma unroll
        for (int j = 0; j < 8; j++)
            if ((key[j] & maskdone) == prefix)
                atomicAdd(&h0[(key[j] >> shifts[p]) & bmask], 1);
        __syncthreads();
        // inclusive suffix scan (Hillis-Steele, ping-pong)
        int* src = h0; int* dst = h1;
        for (int off = 1; off < nb; off <<= 1) {
            for (int bb = tid; bb < nb; bb += 1024)
                dst[bb] = src[bb] + ((bb + off < nb) ? src[bb + off] : 0);
            __syncthreads();
            int* t = src; src = dst; dst = t;
        }
        // find crossing bin: suffix[B] >= krem > suffix[B+1]
        for (int bb = tid; bb < nb; bb += 1024) {
            int sb    = src[bb];
            int snext = (bb + 1 < nb) ? src[bb + 1] : 0;
            if (sb >= krem && snext < krem) { s_B = (unsigned)bb; s_after = snext; }
        }
        __syncthreads();
        prefix   |= s_B << shifts[p];
        maskdone |= bmask << shifts[p];
        krem     -= s_after;
        __syncthreads();
    }

    unsigned T = prefix;        // exact key of K-th largest
    int tie_keep = krem;        // how many ==T to keep (lowest indices first)

    // --- flags + scans -> emit idx ascending ---
    int myeq = 0;
#pragma unroll
    for (int j = 0; j < 8; j++) myeq += (key[j] == T);
    int eq_before = block_exscan(myeq, s_warp);

    bool keep[8];
    int e = eq_before, mykeep = 0;
#pragma unroll
    for (int j = 0; j < 8; j++) {
        if (key[j] == T) { keep[j] = (e < tie_keep); e++; }
        else             { keep[j] = (key[j] > T); }
        mykeep += keep[j];
    }
    int pos = block_exscan(mykeep, s_warp);
#pragma unroll
    for (int j = 0; j < 8; j++)
        if (keep[j]) g_idx[pos++] = tid * 8 + j;

    if (tid == 0) g_inv_norm = inv_norm;
}

// ---------------------------------------------------------------------------
// Kernel C: X_pooled[r] = X[idx[r]] * tanh(y[idx[r]] * inv_norm)
// ---------------------------------------------------------------------------
__global__ __launch_bounds__(128) void gather_x_kernel(
    const float* __restrict__ X, float* __restrict__ out)
{
    int r   = blockIdx.x;               // 4096 blocks
    int row = g_idx[r];
    float gate = tanhf(g_y[row] * g_inv_norm);
    const float4* xr = (const float4*)(X + (size_t)row * F_DIM);
    float4* o = (float4*)(out + (size_t)r * F_DIM);
    float4 x = xr[threadIdx.x];         // 128 float4 per row
    float4 w = {x.x * gate, x.y * gate, x.z * gate, x.w * gate};
    o[threadIdx.x] = w;
}

// ---------------------------------------------------------------------------
// Kernel D: A_pooled[r][c] = A[idx[r]][idx[c]]   (dominant, HBM-bound)
// ---------------------------------------------------------------------------
__global__ __launch_bounds__(256) void gather_a_kernel(
    const float* __restrict__ A, float* __restrict__ outA)
{
    int r = blockIdx.x;                 // 4096 blocks
    const float* rowp = A + (size_t)g_idx[r] * N_ROWS;
    const int4* idx4 = (const int4*)g_idx;
    float4* o = (float4*)(outA + (size_t)r * K_KEEP);
#pragma unroll 4
    for (int c = threadIdx.x; c < K_KEEP / 4; c += 256) {
        int4 i = __ldg(&idx4[c]);
        float4 v;
        v.x = __ldg(&rowp[i.x]);
        v.y = __ldg(&rowp[i.y]);
        v.z = __ldg(&rowp[i.z]);
        v.w = __ldg(&rowp[i.w]);
        o[c] = v;
    }
}

// ---------------------------------------------------------------------------
extern "C" void kernel_launch(void* const* d_in, const int* in_sizes, int n_in,
                              void* d_out, int out_size)
{
    const float* X    = (const float*)d_in[0];
    const float* A    = (const float*)d_in[1];
    const float* kern = (const float*)d_in[2];
    float* out = (float*)d_out;

    compute_y_kernel<<<N_ROWS / 8, 256>>>(X, kern);
    select_kernel<<<1, 1024>>>(kern);
    gather_x_kernel<<<K_KEEP, 128>>>(X, out);
    gather_a_kernel<<<K_KEEP, 256>>>(A, out + (size_t)K_KEEP * F_DIM);
}

// round 2
// speedup vs baseline: 1.2605x; 1.2605x over previous
#include <cuda_runtime.h>
#include <cuda_bf16.h>

#define N_ROWS 8192
#define F_DIM  512
#define K_KEEP 4096

// Scratch (device globals — no allocation allowed)
__device__ __align__(16) float g_y[N_ROWS];     // unnormalized scores X @ kernel
__device__ float g_inv_norm;                    // 1/||kernel||
__device__ __align__(16) int   g_idx[K_KEEP];   // kept indices, ascending

// ---------------------------------------------------------------------------
// Kernel A: y[row] = dot(X[row], kernel)   (one warp per row)
// ---------------------------------------------------------------------------
__global__ __launch_bounds__(256) void compute_y_kernel(
    const float* __restrict__ X, const float* __restrict__ kern)
{
    int warp = threadIdx.x >> 5;
    int lane = threadIdx.x & 31;
    int row  = blockIdx.x * 8 + warp;   // grid = 1024 blocks
    const float4* x4 = (const float4*)(X + (size_t)row * F_DIM);
    const float4* k4 = (const float4*)kern;
    float acc = 0.f;
#pragma unroll
    for (int it = 0; it < 4; it++) {
        int j = lane + 32 * it;         // 128 float4 per row
        float4 x = x4[j];
        float4 k = __ldg(&k4[j]);
        acc = fmaf(x.x, k.x, acc);
        acc = fmaf(x.y, k.y, acc);
        acc = fmaf(x.z, k.z, acc);
        acc = fmaf(x.w, k.w, acc);
    }
#pragma unroll
    for (int o = 16; o > 0; o >>= 1)
        acc += __shfl_xor_sync(0xFFFFFFFFu, acc, o);
    if (lane == 0) g_y[row] = acc;
}

// ---------------------------------------------------------------------------
// Block exclusive scan helpers (1024 threads)
// ---------------------------------------------------------------------------
__device__ __forceinline__ int block_exscan(int v, int* s_warp)
{
    __syncthreads();                    // protect s_warp reuse across calls
    int lane = threadIdx.x & 31, warp = threadIdx.x >> 5;
    int incl = v;
#pragma unroll
    for (int o = 1; o < 32; o <<= 1) {
        int t = __shfl_up_sync(0xFFFFFFFFu, incl, o);
        if (lane >= o) incl += t;
    }
    if (lane == 31) s_warp[warp] = incl;
    __syncthreads();
    if (warp == 0) {
        int w  = s_warp[lane];
        int wi = w;
#pragma unroll
        for (int o = 1; o < 32; o <<= 1) {
            int t = __shfl_up_sync(0xFFFFFFFFu, wi, o);
            if (lane >= o) wi += t;
        }
        s_warp[lane] = wi - w;          // exclusive warp offset
    }
    __syncthreads();
    return s_warp[warp] + incl - v;     // exclusive for this thread
}

__device__ __forceinline__ int block_exscan_tot(int v, int* s_warp, int* s_tot)
{
    __syncthreads();
    int lane = threadIdx.x & 31, warp = threadIdx.x >> 5;
    int incl = v;
#pragma unroll
    for (int o = 1; o < 32; o <<= 1) {
        int t = __shfl_up_sync(0xFFFFFFFFu, incl, o);
        if (lane >= o) incl += t;
    }
    if (lane == 31) s_warp[warp] = incl;
    __syncthreads();
    if (warp == 0) {
        int w  = s_warp[lane];
        int wi = w;
#pragma unroll
        for (int o = 1; o < 32; o <<= 1) {
            int t = __shfl_up_sync(0xFFFFFFFFu, wi, o);
            if (lane >= o) wi += t;
        }
        if (lane == 31) *s_tot = wi;    // block-wide total
        s_warp[lane] = wi - w;          // exclusive warp offset
    }
    __syncthreads();
    return s_warp[warp] + incl - v;
}

// ---------------------------------------------------------------------------
// Kernel B: single block. Radix-select exact K-th largest key, emit idx[]
// (ascending), compute inv_norm.  Fast hierarchical scans (3 syncs/pass).
// ---------------------------------------------------------------------------
__global__ __launch_bounds__(1024) void select_kernel(const float* __restrict__ kern)
{
    __shared__ int h[2048];
    __shared__ int s_warp[32];
    __shared__ int s_tot;
    __shared__ float s_red[32];
    __shared__ unsigned s_B;
    __shared__ int s_after;

    int tid  = threadIdx.x;
    int lane = tid & 31, warp = tid >> 5;

    // --- load 8 keys per thread (contiguous indices tid*8 .. tid*8+7) ---
    const float4* y4 = (const float4*)g_y;
    float4 a = y4[tid * 2 + 0];
    float4 b = y4[tid * 2 + 1];
    float v[8] = {a.x, a.y, a.z, a.w, b.x, b.y, b.z, b.w};
    unsigned key[8];
#pragma unroll
    for (int j = 0; j < 8; j++) {
        unsigned u = __float_as_uint(v[j]);
        key[j] = (u & 0x80000000u) ? ~u : (u | 0x80000000u); // larger float -> larger key
    }

    // --- inv_norm of kernel vector ---
    float s = 0.f;
    if (tid < F_DIM) { float kv = kern[tid]; s = kv * kv; }
#pragma unroll
    for (int o = 16; o > 0; o >>= 1) s += __shfl_xor_sync(0xFFFFFFFFu, s, o);
    if (lane == 0) s_red[warp] = s;
    __syncthreads();
    if (warp == 0) {
        float t = s_red[lane];
#pragma unroll
        for (int o = 16; o > 0; o >>= 1) t += __shfl_xor_sync(0xFFFFFFFFu, t, o);
        if (lane == 0) s_red[0] = rsqrtf(t);
    }
    __syncthreads();
    float inv_norm = s_red[0];

    // --- 3-pass radix select for exact K-th largest key ---
    const int shifts[3] = {21, 10, 0};
    const int nbv[3]    = {2048, 2048, 1024};
    unsigned prefix = 0, maskdone = 0;
    int krem = K_KEEP;

#pragma unroll 1
    for (int p = 0; p < 3; p++) {
        int nb = nbv[p];
        int shift = shifts[p];
        unsigned bmask = (unsigned)(nb - 1);
        h[tid] = 0; h[tid + 1024] = 0;
        __syncthreads();
#pragma unroll
        for (int j = 0; j < 8; j++)
            if ((key[j] & maskdone) == prefix)
                atomicAdd(&h[(key[j] >> shift) & bmask], 1);
        __syncthreads();

        // hierarchical exclusive scan over nb bins
        int v0, v1, tsum;
        if (nb == 2048) { v0 = h[2 * tid]; v1 = h[2 * tid + 1]; tsum = v0 + v1; }
        else            { v0 = h[tid];     v1 = 0;              tsum = v0; }
        int ex = block_exscan_tot(tsum, s_warp, &s_tot);
        int total = s_tot;

        // crossing bin: suffix[B] >= krem > suffix[B+1]
        if (nb == 2048) {
            int suf0 = total - ex;
            int suf1 = suf0 - v0;
            int suf2 = suf1 - v1;
            if (suf0 >= krem && suf1 < krem) { s_B = (unsigned)(2 * tid);     s_after = suf1; }
            if (suf1 >= krem && suf2 < krem) { s_B = (unsigned)(2 * tid + 1); s_after = suf2; }
        } else {
            int suf0 = total - ex;
            int suf1 = suf0 - v0;
            if (suf0 >= krem && suf1 < krem) { s_B = (unsigned)tid; s_after = suf1; }
        }
        __syncthreads();
        prefix   |= s_B << shift;
        maskdone |= bmask << shift;
        krem     -= s_after;
        __syncthreads();
    }

    unsigned T = prefix;        // exact key of K-th largest
    int tie_keep = krem;        // how many ==T to keep (lowest indices first)

    // --- flags + scans -> emit idx ascending ---
    int myeq = 0;
#pragma unroll
    for (int j = 0; j < 8; j++) myeq += (key[j] == T);
    int eq_before = block_exscan(myeq, s_warp);

    bool keep[8];
    int e = eq_before, mykeep = 0;
#pragma unroll
    for (int j = 0; j < 8; j++) {
        if (key[j] == T) { keep[j] = (e < tie_keep); e++; }
        else             { keep[j] = (key[j] > T); }
        mykeep += keep[j];
    }
    int pos = block_exscan(mykeep, s_warp);
#pragma unroll
    for (int j = 0; j < 8; j++)
        if (keep[j]) g_idx[pos++] = tid * 8 + j;

    if (tid == 0) g_inv_norm = inv_norm;
}

// ---------------------------------------------------------------------------
// Kernel C: fused gather.
//   blocks [0, 2048):   X_pooled — 2 rows per block, tanh gating
//   blocks [2048, 6144): A_pooled — one A-row gather per block (HBM-bound)
// ---------------------------------------------------------------------------
__global__ __launch_bounds__(256) void gather_kernel(
    const float* __restrict__ X, const float* __restrict__ A,
    float* __restrict__ out)
{
    int bid = blockIdx.x;
    int tid = threadIdx.x;
    if (bid < 2048) {
        int r   = bid * 2 + (tid >> 7);
        int t   = tid & 127;
        int row = g_idx[r];
        float gate = tanhf(g_y[row] * g_inv_norm);
        const float4* xr = (const float4*)(X + (size_t)row * F_DIM);
        float4* o = (float4*)(out + (size_t)r * F_DIM);
        float4 x = xr[t];                // 128 float4 per row
        o[t] = make_float4(x.x * gate, x.y * gate, x.z * gate, x.w * gate);
    } else {
        int r = bid - 2048;
        const float* rowp = A + (size_t)g_idx[r] * N_ROWS;
        const int4* idx4 = (const int4*)g_idx;
        float4* o = (float4*)(out + (size_t)K_KEEP * F_DIM + (size_t)r * K_KEEP);
#pragma unroll
        for (int it = 0; it < 4; it++) {
            int c = tid + it * 256;
            int4 i = __ldg(&idx4[c]);
            float4 v;
            v.x = __ldcs(&rowp[i.x]);
            v.y = __ldcs(&rowp[i.y]);
            v.z = __ldcs(&rowp[i.z]);
            v.w = __ldcs(&rowp[i.w]);
            __stcs(&o[c], v);
        }
    }
}

// ---------------------------------------------------------------------------
extern "C" void kernel_launch(void* const* d_in, const int* in_sizes, int n_in,
                              void* d_out, int out_size)
{
    const float* X    = (const float*)d_in[0];
    const float* A    = (const float*)d_in[1];
    const float* kern = (const float*)d_in[2];
    float* out = (float*)d_out;

    compute_y_kernel<<<N_ROWS / 8, 256>>>(X, kern);
    select_kernel<<<1, 1024>>>(kern);
    gather_kernel<<<2048 + K_KEEP, 256>>>(X, A, out);
}